// round 2
// baseline (speedup 1.0000x reference)
#include <cuda_runtime.h>

#define NN 50000
#define E0 1600000
#define ET 1650000   // E0 + NN self loops

// ---- scratch (static __device__, no allocation) ----
__device__ int    g_is64;
__device__ int    g_count[NN];
__device__ int    g_off[NN + 1];
__device__ int    g_cursor[NN];
__device__ int    g_src[ET];
__device__ float4 g_p[NN];          // pos features (cols 0,1,14), padded to float4
__device__ float  g_h[NN * 64];     // intermediate node features
__device__ float  g_stats[6][128];  // per-layer [sum(64), sumsq(64)]

// ---------------------------------------------------------------------------
// Detect whether edge_index is int64 or int32. For int64 (values < 2^31,
// nonnegative) every odd 32-bit word is the zero high-half. For int32 data the
// odd words are random node ids — 256 consecutive zeros is impossible.
__global__ void k_detect(const int* __restrict__ ei_words) {
    if (threadIdx.x == 0 && blockIdx.x == 0) {
        int all_zero = 1;
        for (int i = 0; i < 256; i++) {
            if (ei_words[2 * i + 1] != 0) { all_zero = 0; break; }
        }
        g_is64 = all_zero;
    }
}

__device__ __forceinline__ int load_idx(const void* __restrict__ ei, int is64, int i) {
    int v = is64 ? (int)((const long long*)ei)[i] : ((const int*)ei)[i];
    // clamp: never crash on a bad read; wrong dtype shows up as rel_err instead
    v = (v < 0) ? 0 : (v >= NN ? NN - 1 : v);
    return v;
}

__global__ void k_zero() {
    int i = blockIdx.x * blockDim.x + threadIdx.x;
    if (i < NN) g_count[i] = 0;
    if (i < 6 * 128) ((float*)g_stats)[i] = 0.f;
}

__global__ void k_hist(const void* __restrict__ ei) {
    int e = blockIdx.x * blockDim.x + threadIdx.x;
    if (e >= ET) return;
    int is64 = g_is64;
    int dst = (e < E0) ? load_idx(ei, is64, E0 + e) : (e - E0);
    atomicAdd(&g_count[dst], 1);
}

// single-block exclusive scan over 50k counts (chunked Hillis-Steele)
__global__ void k_scan() {
    __shared__ int sh[1024];
    __shared__ int srun;
    int tid = threadIdx.x;
    if (tid == 0) srun = 0;
    __syncthreads();
    for (int base = 0; base < NN; base += 1024) {
        int i = base + tid;
        int v = (i < NN) ? g_count[i] : 0;
        sh[tid] = v;
        __syncthreads();
        for (int d = 1; d < 1024; d <<= 1) {
            int t = (tid >= d) ? sh[tid - d] : 0;
            __syncthreads();
            sh[tid] += t;
            __syncthreads();
        }
        int run = srun;
        if (i < NN) {
            int ex = run + sh[tid] - v;
            g_off[i]    = ex;
            g_cursor[i] = ex;
        }
        __syncthreads();
        if (tid == 1023) srun = run + sh[1023];
        __syncthreads();
    }
    if (tid == 0) g_off[NN] = ET;
}

__global__ void k_scatter(const void* __restrict__ ei) {
    int e = blockIdx.x * blockDim.x + threadIdx.x;
    if (e >= ET) return;
    int is64 = g_is64;
    int src, dst;
    if (e < E0) { src = load_idx(ei, is64, e); dst = load_idx(ei, is64, E0 + e); }
    else        { src = e - E0;                dst = src; }
    int pos = atomicAdd(&g_cursor[dst], 1);
    if (pos >= 0 && pos < ET) g_src[pos] = src;
}

__global__ void k_p0(const float* __restrict__ x) {
    int n = blockIdx.x * blockDim.x + threadIdx.x;
    if (n >= NN) return;
    g_p[n] = make_float4(x[n * 16 + 0], x[n * 16 + 1], x[n * 16 + 14], 0.f);
}

// ---------------------------------------------------------------------------
// One warp per node. Lane owns channels (2*lane, 2*lane+1).
// Edge phase: acc += relu([p_src-p_dst, p_dst] @ W1 + b1)  (6 FMA per channel)
// Node phase: out = acc_vec @ W2 + deg*b2   (W2 staged in smem, acc via smem)
// Also accumulates per-channel sum/sumsq for BN (block-reduced, then atomics).
__global__ __launch_bounds__(256) void k_conv(
    const float* __restrict__ W1, const float* __restrict__ b1,
    const float* __restrict__ W2, const float* __restrict__ b2,
    float* __restrict__ out_ext, int layer, int do_stats)
{
    __shared__ float sW2[4096];
    __shared__ float sS[8][64];
    __shared__ float sSum[64], sSq[64];

    float* out = out_ext ? out_ext : g_h;
    int tid = threadIdx.x, lane = tid & 31, w = tid >> 5;

    for (int i = tid; i < 4096; i += 256) sW2[i] = W2[i];
    if (tid < 64) { sSum[tid] = 0.f; sSq[tid] = 0.f; }

    int c0 = lane * 2;
    float w1a[6], w1b[6];
#pragma unroll
    for (int k = 0; k < 6; k++) {
        w1a[k] = W1[k * 64 + c0];
        w1b[k] = W1[k * 64 + c0 + 1];
    }
    float b1a = b1[c0], b1b = b1[c0 + 1];
    float b2a = b2[c0], b2b = b2[c0 + 1];
    __syncthreads();

    int gw = blockIdx.x * 8 + w, nw = gridDim.x * 8;
    for (int n = gw; n < NN; n += nw) {
        int s0 = g_off[n], s1 = g_off[n + 1];
        float4 pi = g_p[n];
        float acc0 = 0.f, acc1 = 0.f;

        int e = s0;
        // 2x software pipeline for MLP on the dependent idx->gather chain
        for (; e + 1 < s1; e += 2) {
            int sa = g_src[e], sb = g_src[e + 1];
            float4 pa = g_p[sa];
            float4 pb = g_p[sb];
            {
                float m0 = pa.x - pi.x, m1 = pa.y - pi.y, m2 = pa.z - pi.z;
                float t0 = fmaf(m0, w1a[0], fmaf(m1, w1a[1], fmaf(m2, w1a[2],
                           fmaf(pi.x, w1a[3], fmaf(pi.y, w1a[4], fmaf(pi.z, w1a[5], b1a))))));
                float t1 = fmaf(m0, w1b[0], fmaf(m1, w1b[1], fmaf(m2, w1b[2],
                           fmaf(pi.x, w1b[3], fmaf(pi.y, w1b[4], fmaf(pi.z, w1b[5], b1b))))));
                acc0 += fmaxf(t0, 0.f);
                acc1 += fmaxf(t1, 0.f);
            }
            {
                float m0 = pb.x - pi.x, m1 = pb.y - pi.y, m2 = pb.z - pi.z;
                float t0 = fmaf(m0, w1a[0], fmaf(m1, w1a[1], fmaf(m2, w1a[2],
                           fmaf(pi.x, w1a[3], fmaf(pi.y, w1a[4], fmaf(pi.z, w1a[5], b1a))))));
                float t1 = fmaf(m0, w1b[0], fmaf(m1, w1b[1], fmaf(m2, w1b[2],
                           fmaf(pi.x, w1b[3], fmaf(pi.y, w1b[4], fmaf(pi.z, w1b[5], b1b))))));
                acc0 += fmaxf(t0, 0.f);
                acc1 += fmaxf(t1, 0.f);
            }
        }
        if (e < s1) {
            int sa = g_src[e];
            float4 pa = g_p[sa];
            float m0 = pa.x - pi.x, m1 = pa.y - pi.y, m2 = pa.z - pi.z;
            float t0 = fmaf(m0, w1a[0], fmaf(m1, w1a[1], fmaf(m2, w1a[2],
                       fmaf(pi.x, w1a[3], fmaf(pi.y, w1a[4], fmaf(pi.z, w1a[5], b1a))))));
            float t1 = fmaf(m0, w1b[0], fmaf(m1, w1b[1], fmaf(m2, w1b[2],
                       fmaf(pi.x, w1b[3], fmaf(pi.y, w1b[4], fmaf(pi.z, w1b[5], b1b))))));
            acc0 += fmaxf(t0, 0.f);
            acc1 += fmaxf(t1, 0.f);
        }

        sS[w][c0]     = acc0;
        sS[w][c0 + 1] = acc1;
        __syncwarp();

        float deg = (float)(s1 - s0);
        float o0 = deg * b2a, o1 = deg * b2b;
#pragma unroll 16
        for (int k = 0; k < 64; k++) {
            float sk = sS[w][k];
            float2 wv = ((const float2*)(sW2 + k * 64))[lane];
            o0 = fmaf(sk, wv.x, o0);
            o1 = fmaf(sk, wv.y, o1);
        }
        ((float2*)(out + (size_t)n * 64))[lane] = make_float2(o0, o1);

        if (do_stats) {
            atomicAdd(&sSum[c0], o0);      atomicAdd(&sSum[c0 + 1], o1);
            atomicAdd(&sSq[c0],  o0 * o0); atomicAdd(&sSq[c0 + 1],  o1 * o1);
        }
        __syncwarp();   // protect sS reads before next iteration's overwrite
    }

    if (do_stats) {
        __syncthreads();
        if (tid < 64) {
            atomicAdd(&g_stats[layer][tid],      sSum[tid]);
            atomicAdd(&g_stats[layer][64 + tid], sSq[tid]);
        }
    }
}

// ---------------------------------------------------------------------------
__global__ void k_bn(const float* __restrict__ gamma, const float* __restrict__ beta,
                     int layer)
{
    int i = blockIdx.x * blockDim.x + threadIdx.x;
    if (i >= NN * 64) return;
    int c = i & 63, n = i >> 6;
    float mu  = g_stats[layer][c] * (1.0f / NN);
    float var = g_stats[layer][64 + c] * (1.0f / NN) - mu * mu;
    float v = (g_h[i] - mu) * rsqrtf(var + 1e-5f) * gamma[c] + beta[c];
    v = fmaxf(v, 0.f);
    g_h[i] = v;
    if (c == 0)       g_p[n].x = v;
    else if (c == 1)  g_p[n].y = v;
    else if (c == 14) g_p[n].z = v;
}

// ---------------------------------------------------------------------------
extern "C" void kernel_launch(void* const* d_in, const int* in_sizes, int n_in,
                              void* d_out, int out_size)
{
    const float* x     = (const float*)d_in[0];
    const void*  ei    = d_in[1];
    const float* W1    = (const float*)d_in[2];
    const float* b1    = (const float*)d_in[3];
    const float* W2    = (const float*)d_in[4];
    const float* b2    = (const float*)d_in[5];
    const float* gamma = (const float*)d_in[6];
    const float* beta  = (const float*)d_in[7];
    float* out = (float*)d_out;

    k_detect <<<1, 32>>>((const int*)ei);
    k_zero   <<<(NN + 255) / 256, 256>>>();
    k_hist   <<<(ET + 255) / 256, 256>>>(ei);
    k_scan   <<<1, 1024>>>();
    k_scatter<<<(ET + 255) / 256, 256>>>(ei);
    k_p0     <<<(NN + 255) / 256, 256>>>(x);

    for (int l = 0; l < 6; l++) {
        k_conv<<<1024, 256>>>(W1 + l * 384, b1 + l * 64,
                              W2 + l * 4096, b2 + l * 64,
                              (l == 5) ? out : nullptr, l, (l < 5) ? 1 : 0);
        if (l < 5)
            k_bn<<<(NN * 64 + 255) / 256, 256>>>(gamma + l * 64, beta + l * 64, l);
    }
}

// round 3
// speedup vs baseline: 2.0843x; 2.0843x over previous
#include <cuda_runtime.h>

#define NN 50000
#define E0 1600000
#define ET 1650000           // E0 + NN self loops
#define NB 196               // ceil(NN/256)

// ---- scratch (static __device__, no allocation) ----
__device__ int    g_is64;
__device__ int    g_count[NN];
__device__ int    g_bsum[NB];
__device__ int    g_boff[NB];
__device__ int    g_off[NN + 1];
__device__ int    g_cursor[NN];
__device__ int    g_src[ET];
__device__ float4 g_pb[2][NN];      // double-buffered node features (cols 0,1,14)
__device__ float  g_stats[6][8];    // per-layer [sum0,sum1,sum2, sq0,sq1,sq2]

// ---- packed f32x2 helpers (sm_100+) -----------------------------------
__device__ __forceinline__ unsigned long long pk2(float a, float b) {
    unsigned long long r;
    asm("mov.b64 %0, {%1, %2};" : "=l"(r) : "r"(__float_as_uint(a)), "r"(__float_as_uint(b)));
    return r;
}
__device__ __forceinline__ void upk2(unsigned long long v, float& a, float& b) {
    unsigned int lo, hi;
    asm("mov.b64 {%0, %1}, %2;" : "=r"(lo), "=r"(hi) : "l"(v));
    a = __uint_as_float(lo); b = __uint_as_float(hi);
}
__device__ __forceinline__ unsigned long long ffma2(unsigned long long a, unsigned long long b, unsigned long long c) {
    unsigned long long r;
    asm("fma.rn.f32x2 %0, %1, %2, %3;" : "=l"(r) : "l"(a), "l"(b), "l"(c));
    return r;
}
__device__ __forceinline__ unsigned long long fadd2(unsigned long long a, unsigned long long b) {
    unsigned long long r;
    asm("add.rn.f32x2 %0, %1, %2;" : "=l"(r) : "l"(a), "l"(b));
    return r;
}

// ---------------------------------------------------------------------------
__global__ void k_detect(const int* __restrict__ ei_words) {
    if (threadIdx.x == 0 && blockIdx.x == 0) {
        int all_zero = 1;
        for (int i = 0; i < 256; i++)
            if (ei_words[2 * i + 1] != 0) { all_zero = 0; break; }
        g_is64 = all_zero;
    }
}

__device__ __forceinline__ int load_idx(const void* __restrict__ ei, int is64, int i) {
    int v = is64 ? (int)((const long long*)ei)[i] : ((const int*)ei)[i];
    v = (v < 0) ? 0 : (v >= NN ? NN - 1 : v);
    return v;
}

__global__ void k_zero() {
    int i = blockIdx.x * blockDim.x + threadIdx.x;
    if (i < NN) g_count[i] = 1;               // self-loop pre-counted
    if (i < 6 * 8) ((float*)g_stats)[i] = 0.f;
}

__global__ void k_hist(const void* __restrict__ ei) {
    int e = blockIdx.x * blockDim.x + threadIdx.x;
    if (e >= E0) return;
    int dst = load_idx(ei, g_is64, E0 + e);
    atomicAdd(&g_count[dst], 1);
}

// ---- 3-kernel scan --------------------------------------------------------
__global__ void k_scanA() {
    __shared__ int sh[256];
    int b = blockIdx.x, tid = threadIdx.x;
    int i = b * 256 + tid;
    sh[tid] = (i < NN) ? g_count[i] : 0;
    __syncthreads();
    for (int d = 128; d > 0; d >>= 1) {
        if (tid < d) sh[tid] += sh[tid + d];
        __syncthreads();
    }
    if (tid == 0) g_bsum[b] = sh[0];
}
__global__ void k_scanB() {
    __shared__ int sh[256];
    int tid = threadIdx.x;
    int v = (tid < NB) ? g_bsum[tid] : 0;
    sh[tid] = v;
    __syncthreads();
    for (int d = 1; d < 256; d <<= 1) {
        int t = (tid >= d) ? sh[tid - d] : 0;
        __syncthreads();
        sh[tid] += t;
        __syncthreads();
    }
    if (tid < NB) g_boff[tid] = sh[tid] - v;
    if (tid == 0) g_off[NN] = ET;
}
__global__ void k_scanC() {
    __shared__ int sh[256];
    int b = blockIdx.x, tid = threadIdx.x;
    int i = b * 256 + tid;
    int v = (i < NN) ? g_count[i] : 0;
    sh[tid] = v;
    __syncthreads();
    for (int d = 1; d < 256; d <<= 1) {
        int t = (tid >= d) ? sh[tid - d] : 0;
        __syncthreads();
        sh[tid] += t;
        __syncthreads();
    }
    if (i < NN) {
        int ex = g_boff[b] + sh[tid] - v;
        g_off[i]    = ex;
        g_cursor[i] = ex;
    }
}

__global__ void k_scatter(const void* __restrict__ ei) {
    int e = blockIdx.x * blockDim.x + threadIdx.x;
    if (e >= ET) return;
    int is64 = g_is64;
    int src, dst;
    if (e < E0) { src = load_idx(ei, is64, e); dst = load_idx(ei, is64, E0 + e); }
    else        { src = e - E0;                dst = src; }
    int pos = atomicAdd(&g_cursor[dst], 1);
    if (pos >= 0 && pos < ET) g_src[pos] = src;
}

__global__ void k_p0(const float* __restrict__ x) {
    int n = blockIdx.x * blockDim.x + threadIdx.x;
    if (n >= NN) return;
    g_pb[0][n] = make_float4(x[n * 16 + 0], x[n * 16 + 1], x[n * 16 + 14], 0.f);
}

// ---------------------------------------------------------------------------
__global__ __launch_bounds__(256) void k_conv(
    const float* __restrict__ W1, const float* __restrict__ b1,
    const float* __restrict__ W2, const float* __restrict__ b2,
    float* __restrict__ out, int layer)
{
    __shared__ float sbuf[8][32][8];
    __shared__ float sW2[4096];
    __shared__ float sS[8][64];
    __shared__ float sStat[6];

    const int mode = (layer < 5) ? 0 : 5;
    const float4* __restrict__ pin = g_pb[layer & 1];
    float4* __restrict__ pnext = g_pb[(layer + 1) & 1];

    int tid = threadIdx.x, lane = tid & 31, w = tid >> 5;
    int c0 = lane * 2;

    if (tid < 6) sStat[tid] = 0.f;
    if (mode == 5)
        for (int i = tid; i < 4096; i += 256) sW2[i] = W2[i];

    unsigned long long wpx = pk2(W1[0 * 64 + c0], W1[0 * 64 + c0 + 1]);
    unsigned long long wpy = pk2(W1[1 * 64 + c0], W1[1 * 64 + c0 + 1]);
    unsigned long long wpz = pk2(W1[2 * 64 + c0], W1[2 * 64 + c0 + 1]);
    float dAx = W1[3 * 64 + c0] - W1[0 * 64 + c0];
    float dAy = W1[4 * 64 + c0] - W1[1 * 64 + c0];
    float dAz = W1[5 * 64 + c0] - W1[2 * 64 + c0];
    float dBx = W1[3 * 64 + c0 + 1] - W1[0 * 64 + c0 + 1];
    float dBy = W1[4 * 64 + c0 + 1] - W1[1 * 64 + c0 + 1];
    float dBz = W1[5 * 64 + c0 + 1] - W1[2 * 64 + c0 + 1];
    float b1a = b1[c0], b1b = b1[c0 + 1];

    float w2a0 = W2[c0 * 64 + 0],  w2b0 = W2[(c0 + 1) * 64 + 0];
    float w2a1 = W2[c0 * 64 + 1],  w2b1 = W2[(c0 + 1) * 64 + 1];
    float w2aE = W2[c0 * 64 + 14], w2bE = W2[(c0 + 1) * 64 + 14];
    float b2c0 = b2[0], b2c1 = b2[1], b2cE = b2[14];
    float b2a = b2[c0], b2b = b2[c0 + 1];

    float wsum0 = 0.f, wsum1 = 0.f, wsum2 = 0.f;
    float wsq0 = 0.f, wsq1 = 0.f, wsq2 = 0.f;
    __syncthreads();

    int gw = blockIdx.x * 8 + w, nw = gridDim.x * 8;
    for (int n = gw; n < NN; n += nw) {
        int s0 = g_off[n], s1 = g_off[n + 1];
        float4 pi = pin[n];

        float cnA = fmaf(pi.x, dAx, fmaf(pi.y, dAy, fmaf(pi.z, dAz, b1a)));
        float cnB = fmaf(pi.x, dBx, fmaf(pi.y, dBy, fmaf(pi.z, dBz, b1b)));
        unsigned long long cn = pk2(cnA, cnB);
        unsigned long long acc = 0ULL;

        for (int base = s0; base < s1; base += 32) {
            int cnt = s1 - base; if (cnt > 32) cnt = 32;
            if (lane < cnt) {
                int sidx = g_src[base + lane];
                float4 pa = pin[sidx];
                float4* sp = (float4*)&sbuf[w][lane][0];
                sp[0] = make_float4(pa.x, pa.x, pa.y, pa.y);
                sp[1] = make_float4(pa.z, pa.z, 0.f, 0.f);
            }
            __syncwarp();
            if (cnt == 32) {
#pragma unroll 8
                for (int j = 0; j < 32; j++) {
                    const ulonglong2 v01 = *(const ulonglong2*)&sbuf[w][j][0];
                    const unsigned long long vz = *(const unsigned long long*)&sbuf[w][j][4];
                    unsigned long long t = ffma2(v01.x, wpx, cn);
                    t = ffma2(v01.y, wpy, t);
                    t = ffma2(vz,    wpz, t);
                    float ta, tb; upk2(t, ta, tb);
                    ta = fmaxf(ta, 0.f); tb = fmaxf(tb, 0.f);
                    acc = fadd2(acc, pk2(ta, tb));
                }
            } else {
                for (int j = 0; j < cnt; j++) {
                    const ulonglong2 v01 = *(const ulonglong2*)&sbuf[w][j][0];
                    const unsigned long long vz = *(const unsigned long long*)&sbuf[w][j][4];
                    unsigned long long t = ffma2(v01.x, wpx, cn);
                    t = ffma2(v01.y, wpy, t);
                    t = ffma2(vz,    wpz, t);
                    float ta, tb; upk2(t, ta, tb);
                    ta = fmaxf(ta, 0.f); tb = fmaxf(tb, 0.f);
                    acc = fadd2(acc, pk2(ta, tb));
                }
            }
            __syncwarp();
        }

        float acc0, acc1; upk2(acc, acc0, acc1);
        float deg = (float)(s1 - s0);

        if (mode < 5) {
            float p0 = fmaf(acc0, w2a0, acc1 * w2b0);
            float p1 = fmaf(acc0, w2a1, acc1 * w2b1);
            float pE = fmaf(acc0, w2aE, acc1 * w2bE);
#pragma unroll
            for (int off = 16; off > 0; off >>= 1) {
                p0 += __shfl_xor_sync(0xffffffffu, p0, off);
                p1 += __shfl_xor_sync(0xffffffffu, p1, off);
                pE += __shfl_xor_sync(0xffffffffu, pE, off);
            }
            if (lane == 0) {
                float o0 = fmaf(deg, b2c0, p0);
                float o1 = fmaf(deg, b2c1, p1);
                float oE = fmaf(deg, b2cE, pE);
                pnext[n] = make_float4(o0, o1, oE, 0.f);
                wsum0 += o0; wsum1 += o1; wsum2 += oE;
                wsq0 += o0 * o0; wsq1 += o1 * o1; wsq2 += oE * oE;
            }
        } else {
            sS[w][c0] = acc0;
            sS[w][c0 + 1] = acc1;
            __syncwarp();
            float o0 = deg * b2a, o1 = deg * b2b;
#pragma unroll 16
            for (int k = 0; k < 64; k++) {
                float sk = sS[w][k];
                float2 wv = ((const float2*)(sW2 + k * 64))[lane];
                o0 = fmaf(sk, wv.x, o0);
                o1 = fmaf(sk, wv.y, o1);
            }
            ((float2*)(out + (size_t)n * 64))[lane] = make_float2(o0, o1);
            __syncwarp();
        }
    }

    if (mode < 5) {
        if (lane == 0) {
            atomicAdd(&sStat[0], wsum0); atomicAdd(&sStat[1], wsum1); atomicAdd(&sStat[2], wsum2);
            atomicAdd(&sStat[3], wsq0);  atomicAdd(&sStat[4], wsq1);  atomicAdd(&sStat[5], wsq2);
        }
        __syncthreads();
        if (tid < 6) atomicAdd(&g_stats[layer][tid], sStat[tid]);
    }
}

// ---------------------------------------------------------------------------
__global__ void k_bn3(const float* __restrict__ gamma, const float* __restrict__ beta,
                      int layer)
{
    int n = blockIdx.x * blockDim.x + threadIdx.x;
    if (n >= NN) return;
    float4* p = g_pb[(layer + 1) & 1];
    const float inv = 1.0f / NN;
    float mu0 = g_stats[layer][0] * inv, mu1 = g_stats[layer][1] * inv, mu2 = g_stats[layer][2] * inv;
    float v0 = g_stats[layer][3] * inv - mu0 * mu0;
    float v1 = g_stats[layer][4] * inv - mu1 * mu1;
    float v2 = g_stats[layer][5] * inv - mu2 * mu2;
    float4 h = p[n];
    float o0 = fmaxf((h.x - mu0) * rsqrtf(v0 + 1e-5f) * gamma[0]  + beta[0],  0.f);
    float o1 = fmaxf((h.y - mu1) * rsqrtf(v1 + 1e-5f) * gamma[1]  + beta[1],  0.f);
    float o2 = fmaxf((h.z - mu2) * rsqrtf(v2 + 1e-5f) * gamma[14] + beta[14], 0.f);
    p[n] = make_float4(o0, o1, o2, 0.f);
}

// ---------------------------------------------------------------------------
extern "C" void kernel_launch(void* const* d_in, const int* in_sizes, int n_in,
                              void* d_out, int out_size)
{
    const float* x     = (const float*)d_in[0];
    const void*  ei    = d_in[1];
    const float* W1    = (const float*)d_in[2];
    const float* b1    = (const float*)d_in[3];
    const float* W2    = (const float*)d_in[4];
    const float* b2    = (const float*)d_in[5];
    const float* gamma = (const float*)d_in[6];
    const float* beta  = (const float*)d_in[7];
    float* out = (float*)d_out;

    k_detect <<<1, 32>>>((const int*)ei);
    k_zero   <<<(NN + 255) / 256, 256>>>();
    k_hist   <<<(E0 + 255) / 256, 256>>>(ei);
    k_scanA  <<<NB, 256>>>();
    k_scanB  <<<1, 256>>>();
    k_scanC  <<<NB, 256>>>();
    k_scatter<<<(ET + 255) / 256, 256>>>(ei);
    k_p0     <<<(NN + 255) / 256, 256>>>(x);

    for (int l = 0; l < 6; l++) {
        k_conv<<<1024, 256>>>(W1 + l * 384, b1 + l * 64,
                              W2 + l * 4096, b2 + l * 64, out, l);
        if (l < 5)
            k_bn3<<<NB, 256>>>(gamma + l * 64, beta + l * 64, l);
    }
}